// round 15
// baseline (speedup 1.0000x reference)
#include <cuda_runtime.h>
#include <cuda_bf16.h>
#include <math.h>

// Problem constants
#define BB 4
#define LL 4096
#define DD 1024
#define RR 32
#define GG 256
#define MTOK (BB*LL)          // 16384 tokens
#define NSEG 32
#define SEG  (LL/NSEG)        // 128

// ---------------- scratch (static device memory; no allocations) ----------------
__device__ float g_h[MTOK * GG];        // 16 MB : relu(x@W1+b1)
__device__ float g_UV[MTOK * 64];       //  4 MB : cols 0..31 = U, 32..63 = V
__device__ float g_gateU[MTOK * RR];    //  2 MB : sigmoid(h@W2+b2) * U
__device__ float g_glob[MTOK * RR];     //  2 MB : local (per-segment) cumsum of V
__device__ float g_segsum[BB * NSEG * RR];

// ---------------- helpers ----------------
__device__ __forceinline__ unsigned f2tf32(float f) {
    unsigned r;
    asm("cvt.rna.tf32.f32 %0, %1;" : "=r"(r) : "f"(f));
    return r;
}

__device__ __forceinline__ unsigned pack_bf16x2(float lo, float hi) {
    __nv_bfloat162 h2 = __floats2bfloat162_rn(lo, hi);   // lo -> low half
    return *(unsigned*)&h2;
}

__device__ __forceinline__ void mma_tf32(float* d, const unsigned* a, const unsigned* b) {
    asm volatile(
        "mma.sync.aligned.m16n8k8.row.col.f32.tf32.tf32.f32 "
        "{%0,%1,%2,%3}, {%4,%5,%6,%7}, {%8,%9}, {%0,%1,%2,%3};"
        : "+f"(d[0]), "+f"(d[1]), "+f"(d[2]), "+f"(d[3])
        : "r"(a[0]), "r"(a[1]), "r"(a[2]), "r"(a[3]), "r"(b[0]), "r"(b[1]));
}

__device__ __forceinline__ void mma_bf16(float* d, const unsigned* a, const unsigned* b) {
    asm volatile(
        "mma.sync.aligned.m16n8k16.row.col.f32.bf16.bf16.f32 "
        "{%0,%1,%2,%3}, {%4,%5,%6,%7}, {%8,%9}, {%0,%1,%2,%3};"
        : "+f"(d[0]), "+f"(d[1]), "+f"(d[2]), "+f"(d[3])
        : "r"(a[0]), "r"(a[1]), "r"(a[2]), "r"(a[3]), "r"(b[0]), "r"(b[1]));
}

// ======================================================================
// K12 (fused K1+K2a), BF16 mma m16n8k16, double-buffered, BM=128:
//   bx=0:  h[:,0:128]   and U = x@Uw
//   bx=1:  h[:,128:256] and V = x@Vw
// Block 128(M) x 160(N) x 32(K).  8 warps (2x4), warp tile 64x40 (4x5 atoms).
// Prefetch packed to bf16 at load (pa uint2[4], pb uint4[3]) to fit 128 regs.
// ======================================================================
#define F_APADU 20     // u32 per As row (16 used + 4 pad) -> conflict-free frags
#define F_BPADU 168    // u32 per Bs k2-row (160 used + 8 pad)
#define F_BTASKS 640   // 16 k2-rows * 40 col4 groups
__global__ void __launch_bounds__(256, 2) k12_bf16(
    const float* __restrict__ A,      // x       (M x 1024)
    const float* __restrict__ W,      // gate_w1 (1024 x 256)
    const float* __restrict__ bias,   // gate_b1 (256)
    const float* __restrict__ Uw,     // (1024 x 32)
    const float* __restrict__ Vw)     // (1024 x 32)
{
    const int K = DD;
    __shared__ unsigned As[2][128 * F_APADU];  // 2 x 10.2 KB
    __shared__ unsigned Bs[2][16 * F_BPADU];   // 2 x 10.8 KB

    const int tid  = threadIdx.x;
    const int bx   = blockIdx.x;           // 0..1 (h half + U/V select)
    const int by   = blockIdx.y;           // M tile 0..127
    const int wid  = tid >> 5;
    const int lane = tid & 31;
    const int g    = lane >> 2;            // 0..7
    const int t    = lane & 3;             // 0..3
    const int warpM = wid >> 2;            // 0..1 -> 64 rows
    const int warpN = wid & 3;             // 0..3 -> 40 cols

    const float* Aptr  = A + (size_t)by * 128 * K;
    const float* Wptr  = W + bx * 128;
    const float* UVptr = bx ? Vw : Uw;

    const int aRow = tid >> 3;             // 0..31 (x4 -> 128 rows)
    const int aC4  = (tid & 7) * 4;
    const int aK2  = (tid & 7) * 2;

    float acc[4][5][4];
    #pragma unroll
    for (int ma = 0; ma < 4; ma++)
        #pragma unroll
        for (int na = 0; na < 5; na++)
            #pragma unroll
            for (int i = 0; i < 4; i++) acc[ma][na][i] = 0.f;

    uint2 pa[4];
    uint4 pb[3];

    // A loader: row block i, k-offset kf -> packed uint2
    auto loadA = [&](int i, int kf) -> uint2 {
        float4 a4 = *(const float4*)(Aptr + (size_t)(aRow + i * 32) * K + kf + aC4);
        uint2 v;
        v.x = pack_bf16x2(a4.x, a4.y);
        v.y = pack_bf16x2(a4.z, a4.w);
        return v;
    };
    // B loader: task, absolute even k-row kr -> packed uint4
    auto loadB = [&](int task, int krbase) -> uint4 {
        int k2 = task / 40;
        int c4 = (task % 40) * 4;
        const float* base;
        int stride;
        if (c4 < 128) { base = Wptr  + (size_t)(krbase + 2 * k2) * GG + c4;        stride = GG; }
        else          { base = UVptr + (size_t)(krbase + 2 * k2) * 32 + (c4-128);  stride = 32; }
        float4 e = *(const float4*)base;
        float4 o = *(const float4*)(base + stride);
        uint4 v;
        v.x = pack_bf16x2(e.x, o.x);
        v.y = pack_bf16x2(e.y, o.y);
        v.z = pack_bf16x2(e.z, o.z);
        v.w = pack_bf16x2(e.w, o.w);
        return v;
    };

    // prologue (k0 = 0)
    #pragma unroll
    for (int i = 0; i < 4; i++) pa[i] = loadA(i, 0);
    #pragma unroll
    for (int i = 0; i < 3; i++) {
        int task = tid + i * 256;
        if (task < F_BTASKS) pb[i] = loadB(task, 0);
    }

    int p = 0;
    for (int k0 = 0; k0 < K; k0 += 32) {
        // store current tiles into buffer p
        #pragma unroll
        for (int i = 0; i < 4; i++)
            *(uint2*)&As[p][(aRow + i * 32) * F_APADU + aK2] = pa[i];
        #pragma unroll
        for (int i = 0; i < 3; i++) {
            int task = tid + i * 256;
            if (task < F_BTASKS)
                *(uint4*)&Bs[p][(task / 40) * F_BPADU + (task % 40) * 4] = pb[i];
        }
        __syncthreads();

        // prefetch next k-tile (overlaps with mma below)
        if (k0 + 32 < K) {
            #pragma unroll
            for (int i = 0; i < 4; i++) pa[i] = loadA(i, k0 + 32);
            #pragma unroll
            for (int i = 0; i < 3; i++) {
                int task = tid + i * 256;
                if (task < F_BTASKS) pb[i] = loadB(task, k0 + 32);
            }
        }

        // 2 k16 steps over the 32-k tile (reads buffer p)
        #pragma unroll
        for (int ks = 0; ks < 2; ks++) {
            int kb2 = ks * 8;
            unsigned afr[4][4], bfr[5][2];
            #pragma unroll
            for (int ma = 0; ma < 4; ma++) {
                int r0 = warpM * 64 + ma * 16;
                afr[ma][0] = As[p][(r0 + g)     * F_APADU + kb2 + t];
                afr[ma][1] = As[p][(r0 + g + 8) * F_APADU + kb2 + t];
                afr[ma][2] = As[p][(r0 + g)     * F_APADU + kb2 + 4 + t];
                afr[ma][3] = As[p][(r0 + g + 8) * F_APADU + kb2 + 4 + t];
            }
            #pragma unroll
            for (int na = 0; na < 5; na++) {
                int c0 = warpN * 40 + na * 8;
                bfr[na][0] = Bs[p][(kb2 + t)     * F_BPADU + c0 + g];
                bfr[na][1] = Bs[p][(kb2 + 4 + t) * F_BPADU + c0 + g];
            }
            #pragma unroll
            for (int ma = 0; ma < 4; ma++)
                #pragma unroll
                for (int na = 0; na < 5; na++)
                    mma_bf16(acc[ma][na], afr[ma], bfr[na]);
        }
        p ^= 1;
    }

    // epilogue: cols <128 -> bias+relu -> g_h ; cols >=128 -> raw -> g_UV
    #pragma unroll
    for (int ma = 0; ma < 4; ma++) {
        int rbase = by * 128 + warpM * 64 + ma * 16;
        #pragma unroll
        for (int na = 0; na < 5; na++) {
            int colBlk = warpN * 40 + na * 8 + t * 2;     // 0..158
            if (colBlk < 128) {
                int col = bx * 128 + colBlk;
                float b0 = __ldg(bias + col), b1 = __ldg(bias + col + 1);
                float2 v;
                v.x = fmaxf(acc[ma][na][0] + b0, 0.f);
                v.y = fmaxf(acc[ma][na][1] + b1, 0.f);
                *(float2*)&g_h[(size_t)(rbase + g) * GG + col] = v;
                v.x = fmaxf(acc[ma][na][2] + b0, 0.f);
                v.y = fmaxf(acc[ma][na][3] + b1, 0.f);
                *(float2*)&g_h[(size_t)(rbase + g + 8) * GG + col] = v;
            } else {
                int col = bx * 32 + (colBlk - 128);       // U at 0..31, V at 32..63
                float2 v;
                v.x = acc[ma][na][0]; v.y = acc[ma][na][1];
                *(float2*)&g_UV[(size_t)(rbase + g) * 64 + col] = v;
                v.x = acc[ma][na][2]; v.y = acc[ma][na][3];
                *(float2*)&g_UV[(size_t)(rbase + g + 8) * 64 + col] = v;
            }
        }
    }
}

// ======================================================================
// K2b (bf16 mma): gate = sigmoid(h @ W2 + b2); gateU = gate * U
// Block = 64 tokens, 256 threads (8 warps, 2x4), N=32, K=256 (16 k16 steps).
// ======================================================================
#define H2_PADU 132    // u32 per hs row (128 used + 4 pad): bank = 4g+t, distinct
__global__ void __launch_bounds__(256) k2b_mma(
    const float* __restrict__ W2,      // (256 x 32)
    const float* __restrict__ b2)      // (32)
{
    __shared__ unsigned hs[64 * H2_PADU];   // 33.8 KB

    const int tid  = threadIdx.x;
    const int by   = blockIdx.x;            // token tile 0..255
    const int wid  = tid >> 5;
    const int lane = tid & 31;
    const int g    = lane >> 2;             // 0..7
    const int t    = lane & 3;              // 0..3
    const int warpM = wid >> 2;             // 0..1 -> 32 rows
    const int warpN = wid & 3;              // 0..3 -> 8 cols

    const int token0 = by * 64;

    // load h tile (64 x 256 f32) -> packed bf16 smem
    #pragma unroll
    for (int i = 0; i < 16; i++) {
        int flat = tid + i * 256;           // 0..4095
        int row  = flat >> 6;               // 0..63
        int c4   = (flat & 63) * 4;         // 0..252
        float4 v = *(const float4*)(g_h + (size_t)(token0 + row) * GG + c4);
        uint2 pv;
        pv.x = pack_bf16x2(v.x, v.y);
        pv.y = pack_bf16x2(v.z, v.w);
        *(uint2*)&hs[row * H2_PADU + (c4 >> 1)] = pv;
    }
    __syncthreads();

    // gate GEMM: M=64, N=32, K=256
    float acc2[2][4];
    #pragma unroll
    for (int ma = 0; ma < 2; ma++)
        #pragma unroll
        for (int i = 0; i < 4; i++) acc2[ma][i] = 0.f;

    const int n = warpN * 8 + g;
    #pragma unroll
    for (int kstep = 0; kstep < 16; kstep++) {
        int kb2u = kstep * 8;
        unsigned afr[2][4], bfr[2];
        #pragma unroll
        for (int ma = 0; ma < 2; ma++) {
            int r0 = warpM * 32 + ma * 16;
            afr[ma][0] = hs[(r0 + g)     * H2_PADU + kb2u + t];
            afr[ma][1] = hs[(r0 + g + 8) * H2_PADU + kb2u + t];
            afr[ma][2] = hs[(r0 + g)     * H2_PADU + kb2u + 4 + t];
            afr[ma][3] = hs[(r0 + g + 8) * H2_PADU + kb2u + 4 + t];
        }
        int k0f = kstep * 16 + 2 * t;
        bfr[0] = pack_bf16x2(__ldg(W2 + (size_t)k0f * 32 + n),
                             __ldg(W2 + (size_t)(k0f + 1) * 32 + n));
        bfr[1] = pack_bf16x2(__ldg(W2 + (size_t)(k0f + 8) * 32 + n),
                             __ldg(W2 + (size_t)(k0f + 9) * 32 + n));
        #pragma unroll
        for (int ma = 0; ma < 2; ma++)
            mma_bf16(acc2[ma], afr[ma], bfr);
    }

    // epilogue: sigmoid(+b2) * U  -> g_gateU
    #pragma unroll
    for (int ma = 0; ma < 2; ma++) {
        #pragma unroll
        for (int j = 0; j < 4; j++) {
            int rowL = warpM * 32 + ma * 16 + g + (j >> 1) * 8;
            int col  = warpN * 8 + t * 2 + (j & 1);
            float v = acc2[ma][j] + __ldg(b2 + col);
            float gate = 1.f / (1.f + expf(-v));
            float u = __ldg(g_UV + (size_t)(token0 + rowL) * 64 + col);
            g_gateU[(size_t)(token0 + rowL) * RR + col] = gate * u;
        }
    }
}

// ======================================================================
// K3a: segmented inclusive cumsum of V over L (NSEG=32 segments per batch).
// ======================================================================
__global__ void __launch_bounds__(1024) k3a_scan()
{
    const int b   = blockIdx.x >> 5;      // NSEG = 32
    const int seg = blockIdx.x & 31;
    __shared__ float buf[32][33];

    const int tid  = threadIdx.x;
    const int lane = tid & 31;
    const int warp = tid >> 5;
    const int l    = tid >> 5;
    const int r    = tid & 31;

    const float* Vb = g_UV + (size_t)(b * LL + seg * SEG) * 64 + 32;
    float*       Sb = g_glob + (size_t)(b * LL + seg * SEG) * RR;

    float carry = 0.f;
    for (int c = 0; c < SEG / 32; c++) {
        buf[l][r] = Vb[(size_t)(c * 32 + l) * 64 + r];
        __syncthreads();
        float v = buf[lane][warp];
        #pragma unroll
        for (int off = 1; off < 32; off <<= 1) {
            float n = __shfl_up_sync(0xffffffffu, v, off);
            if (lane >= off) v += n;
        }
        v += carry;
        carry = __shfl_sync(0xffffffffu, v, 31);
        buf[lane][warp] = v;
        __syncthreads();
        Sb[c * 1024 + tid] = buf[l][r];
        __syncthreads();
    }
    if (lane == 0)
        g_segsum[(b * NSEG + seg) * RR + warp] = carry;
}

// ======================================================================
// K4: out = (gateU*(S+off)) @ out_w + out_b + depthwise_conv3(x)
// TF32 mma: block = 64 tokens x 128 dcols, K=32 (single tile). (R10 form)
// ======================================================================
#define T4_APAD 36
#define T4_BPAD 136
__global__ void __launch_bounds__(256, 3) k4_mma(
    const float* __restrict__ x,
    const float* __restrict__ conv_w,   // (1024 x 3)
    const float* __restrict__ out_w,    // (32 x 1024)
    const float* __restrict__ out_b,    // (1024)
    float* __restrict__ out)
{
    __shared__ unsigned Gs[64 * T4_APAD];
    __shared__ unsigned Ws[32 * T4_BPAD];

    const int tid  = threadIdx.x;
    const int bx   = blockIdx.x;            // d tile 0..7
    const int by   = blockIdx.y;            // token tile 0..255
    const int wid  = tid >> 5;
    const int lane = tid & 31;
    const int g    = lane >> 2;
    const int tig  = lane & 3;
    const int warpM = wid >> 2;             // 0..1 -> 32 rows
    const int warpN = wid & 3;              // 0..3 -> 32 cols

    const int token0 = by * 64;
    const int d0     = bx * 128;

    const int b   = token0 >> 12;
    const int seg = (token0 & (LL - 1)) >> 7;     // SEG = 128
    const int r   = tid & 31;
    float soff = 0.f;
    for (int s = 0; s < seg; s++)
        soff += g_segsum[(b * NSEG + s) * RR + r];

    #pragma unroll
    for (int i = 0; i < 8; i++) {
        int flat  = tid + i * 256;
        int row   = flat >> 5;
        size_t gi = (size_t)(token0 + row) * RR + r;
        float S = g_glob[gi] + soff;
        Gs[row * T4_APAD + r] = f2tf32(g_gateU[gi] * S);
    }
    #pragma unroll
    for (int i = 0; i < 16; i++) {
        int flat = tid + i * 256;
        int rr   = flat >> 7;
        int c    = flat & 127;
        Ws[rr * T4_BPAD + c] = f2tf32(__ldg(out_w + (size_t)rr * DD + d0 + c));
    }
    __syncthreads();

    float acc[2][4][4];
    #pragma unroll
    for (int ma = 0; ma < 2; ma++)
        #pragma unroll
        for (int na = 0; na < 4; na++)
            #pragma unroll
            for (int i = 0; i < 4; i++) acc[ma][na][i] = 0.f;

    #pragma unroll
    for (int ks = 0; ks < 4; ks++) {
        int kb = ks * 8;
        unsigned afr[2][4], bfr[4][2];
        #pragma unroll
        for (int ma = 0; ma < 2; ma++) {
            int r0 = warpM * 32 + ma * 16;
            afr[ma][0] = Gs[(r0 + g)     * T4_APAD + kb + tig];
            afr[ma][1] = Gs[(r0 + g + 8) * T4_APAD + kb + tig];
            afr[ma][2] = Gs[(r0 + g)     * T4_APAD + kb + tig + 4];
            afr[ma][3] = Gs[(r0 + g + 8) * T4_APAD + kb + tig + 4];
        }
        #pragma unroll
        for (int na = 0; na < 4; na++) {
            int c0 = warpN * 32 + na * 8;
            bfr[na][0] = Ws[(kb + tig)     * T4_BPAD + c0 + g];
            bfr[na][1] = Ws[(kb + tig + 4) * T4_BPAD + c0 + g];
        }
        #pragma unroll
        for (int ma = 0; ma < 2; ma++)
            #pragma unroll
            for (int na = 0; na < 4; na++)
                mma_tf32(acc[ma][na], afr[ma], bfr[na]);
    }

    #pragma unroll
    for (int na = 0; na < 4; na++) {
        int c = d0 + warpN * 32 + na * 8 + tig * 2;
        float2 w01 = *(const float2*)(conv_w + c * 3);
        float2 w23 = *(const float2*)(conv_w + c * 3 + 2);
        float2 w45 = *(const float2*)(conv_w + c * 3 + 4);
        float2 bb  = *(const float2*)(out_b + c);

        #pragma unroll
        for (int ma = 0; ma < 2; ma++) {
            #pragma unroll
            for (int rh = 0; rh < 2; rh++) {
                int token = token0 + warpM * 32 + ma * 16 + g + rh * 8;
                int lpos  = token & (LL - 1);
                const float* xr = x + (size_t)token * DD + c;
                float2 xc = *(const float2*)xr;
                float2 xm = (lpos > 0)      ? *(const float2*)(xr - DD) : make_float2(0.f, 0.f);
                float2 xp = (lpos < LL - 1) ? *(const float2*)(xr + DD) : make_float2(0.f, 0.f);
                float2 o;
                o.x = acc[ma][na][rh * 2 + 0] + bb.x
                    + w01.x * xm.x + w01.y * xc.x + w23.x * xp.x;
                o.y = acc[ma][na][rh * 2 + 1] + bb.y
                    + w23.y * xm.y + w45.x * xc.y + w45.y * xp.y;
                *(float2*)(out + (size_t)token * DD + c) = o;
            }
        }
    }
}

// ======================================================================
extern "C" void kernel_launch(void* const* d_in, const int* in_sizes, int n_in,
                              void* d_out, int out_size)
{
    const float* x       = (const float*)d_in[0];
    const float* gate_w1 = (const float*)d_in[1];
    const float* gate_b1 = (const float*)d_in[2];
    const float* gate_w2 = (const float*)d_in[3];
    const float* gate_b2 = (const float*)d_in[4];
    const float* U_w     = (const float*)d_in[5];
    const float* V_w     = (const float*)d_in[6];
    const float* conv_w  = (const float*)d_in[7];
    const float* out_w   = (const float*)d_in[8];
    const float* out_b   = (const float*)d_in[9];
    float* out = (float*)d_out;

    // K12: h = relu(x@W1+b1) AND UV = x@[Uw|Vw]  (bf16 mma, BM=128)
    k12_bf16<<<dim3(2, MTOK / 128), 256>>>(x, gate_w1, gate_b1, U_w, V_w);
    // K2b: gateU (bf16 mma)
    k2b_mma<<<MTOK / 64, 256>>>(gate_w2, gate_b2);
    // K3a: segmented cumsum of V (totals to g_segsum)
    k3a_scan<<<BB * NSEG, 1024>>>();
    // K4: out = glob@out_w + bias + conv  (tf32 mma; k3c+k3b fused; 64-token tiles)
    k4_mma<<<dim3(DD / 128, MTOK / 64), 256>>>(x, conv_w, out_w, out_b, out);
}

// round 16
// speedup vs baseline: 1.0100x; 1.0100x over previous
#include <cuda_runtime.h>
#include <cuda_bf16.h>
#include <math.h>

// Problem constants
#define BB 4
#define LL 4096
#define DD 1024
#define RR 32
#define GG 256
#define MTOK (BB*LL)          // 16384 tokens
#define NSEG 32
#define SEG  (LL/NSEG)        // 128

// ---------------- scratch (static device memory; no allocations) ----------------
__device__ float g_h[MTOK * GG];        // 16 MB : relu(x@W1+b1)
__device__ float g_UV[MTOK * 64];       //  4 MB : cols 0..31 = U, 32..63 = V
__device__ float g_gateU[MTOK * RR];    //  2 MB : sigmoid(h@W2+b2) * U
__device__ float g_glob[MTOK * RR];     //  2 MB : local (per-segment) cumsum of V
__device__ float g_segsum[BB * NSEG * RR];

// ---------------- helpers ----------------
__device__ __forceinline__ unsigned f2tf32(float f) {
    unsigned r;
    asm("cvt.rna.tf32.f32 %0, %1;" : "=r"(r) : "f"(f));
    return r;
}

__device__ __forceinline__ unsigned pack_bf16x2(float lo, float hi) {
    __nv_bfloat162 h2 = __floats2bfloat162_rn(lo, hi);   // lo -> low half
    return *(unsigned*)&h2;
}

__device__ __forceinline__ void mma_tf32(float* d, const unsigned* a, const unsigned* b) {
    asm volatile(
        "mma.sync.aligned.m16n8k8.row.col.f32.tf32.tf32.f32 "
        "{%0,%1,%2,%3}, {%4,%5,%6,%7}, {%8,%9}, {%0,%1,%2,%3};"
        : "+f"(d[0]), "+f"(d[1]), "+f"(d[2]), "+f"(d[3])
        : "r"(a[0]), "r"(a[1]), "r"(a[2]), "r"(a[3]), "r"(b[0]), "r"(b[1]));
}

__device__ __forceinline__ void mma_bf16(float* d, const unsigned* a, const unsigned* b) {
    asm volatile(
        "mma.sync.aligned.m16n8k16.row.col.f32.bf16.bf16.f32 "
        "{%0,%1,%2,%3}, {%4,%5,%6,%7}, {%8,%9}, {%0,%1,%2,%3};"
        : "+f"(d[0]), "+f"(d[1]), "+f"(d[2]), "+f"(d[3])
        : "r"(a[0]), "r"(a[1]), "r"(a[2]), "r"(a[3]), "r"(b[0]), "r"(b[1]));
}

// ======================================================================
// K12 (fused K1+K2a), BF16 mma m16n8k16, double-buffered, BM=128:
//   bx=0:  h[:,0:128]   and U = x@Uw
//   bx=1:  h[:,128:256] and V = x@Vw
// Block 128(M) x 160(N) x 32(K).  8 warps (2x4), warp tile 64x40 (4x5 atoms).
// Prefetch packed to bf16 at load (pa uint2[4], pb uint4[3]) to fit 128 regs.
// ======================================================================
#define F_APADU 20     // u32 per As row (16 used + 4 pad) -> conflict-free frags
#define F_BPADU 168    // u32 per Bs k2-row (160 used + 8 pad)
#define F_BTASKS 640   // 16 k2-rows * 40 col4 groups
__global__ void __launch_bounds__(256, 2) k12_bf16(
    const float* __restrict__ A,      // x       (M x 1024)
    const float* __restrict__ W,      // gate_w1 (1024 x 256)
    const float* __restrict__ bias,   // gate_b1 (256)
    const float* __restrict__ Uw,     // (1024 x 32)
    const float* __restrict__ Vw)     // (1024 x 32)
{
    const int K = DD;
    __shared__ unsigned As[2][128 * F_APADU];  // 2 x 10.2 KB
    __shared__ unsigned Bs[2][16 * F_BPADU];   // 2 x 10.8 KB

    const int tid  = threadIdx.x;
    const int bx   = blockIdx.x;           // 0..1 (h half + U/V select)
    const int by   = blockIdx.y;           // M tile 0..127
    const int wid  = tid >> 5;
    const int lane = tid & 31;
    const int g    = lane >> 2;            // 0..7
    const int t    = lane & 3;             // 0..3
    const int warpM = wid >> 2;            // 0..1 -> 64 rows
    const int warpN = wid & 3;             // 0..3 -> 40 cols

    const float* Aptr  = A + (size_t)by * 128 * K;
    const float* Wptr  = W + bx * 128;
    const float* UVptr = bx ? Vw : Uw;

    const int aRow = tid >> 3;             // 0..31 (x4 -> 128 rows)
    const int aC4  = (tid & 7) * 4;
    const int aK2  = (tid & 7) * 2;

    float acc[4][5][4];
    #pragma unroll
    for (int ma = 0; ma < 4; ma++)
        #pragma unroll
        for (int na = 0; na < 5; na++)
            #pragma unroll
            for (int i = 0; i < 4; i++) acc[ma][na][i] = 0.f;

    uint2 pa[4];
    uint4 pb[3];

    // A loader: row block i, k-offset kf -> packed uint2
    auto loadA = [&](int i, int kf) -> uint2 {
        float4 a4 = *(const float4*)(Aptr + (size_t)(aRow + i * 32) * K + kf + aC4);
        uint2 v;
        v.x = pack_bf16x2(a4.x, a4.y);
        v.y = pack_bf16x2(a4.z, a4.w);
        return v;
    };
    // B loader: task, absolute even k-row kr -> packed uint4
    auto loadB = [&](int task, int krbase) -> uint4 {
        int k2 = task / 40;
        int c4 = (task % 40) * 4;
        const float* base;
        int stride;
        if (c4 < 128) { base = Wptr  + (size_t)(krbase + 2 * k2) * GG + c4;        stride = GG; }
        else          { base = UVptr + (size_t)(krbase + 2 * k2) * 32 + (c4-128);  stride = 32; }
        float4 e = *(const float4*)base;
        float4 o = *(const float4*)(base + stride);
        uint4 v;
        v.x = pack_bf16x2(e.x, o.x);
        v.y = pack_bf16x2(e.y, o.y);
        v.z = pack_bf16x2(e.z, o.z);
        v.w = pack_bf16x2(e.w, o.w);
        return v;
    };

    // prologue (k0 = 0)
    #pragma unroll
    for (int i = 0; i < 4; i++) pa[i] = loadA(i, 0);
    #pragma unroll
    for (int i = 0; i < 3; i++) {
        int task = tid + i * 256;
        if (task < F_BTASKS) pb[i] = loadB(task, 0);
    }

    int p = 0;
    for (int k0 = 0; k0 < K; k0 += 32) {
        // store current tiles into buffer p
        #pragma unroll
        for (int i = 0; i < 4; i++)
            *(uint2*)&As[p][(aRow + i * 32) * F_APADU + aK2] = pa[i];
        #pragma unroll
        for (int i = 0; i < 3; i++) {
            int task = tid + i * 256;
            if (task < F_BTASKS)
                *(uint4*)&Bs[p][(task / 40) * F_BPADU + (task % 40) * 4] = pb[i];
        }
        __syncthreads();

        // prefetch next k-tile (overlaps with mma below)
        if (k0 + 32 < K) {
            #pragma unroll
            for (int i = 0; i < 4; i++) pa[i] = loadA(i, k0 + 32);
            #pragma unroll
            for (int i = 0; i < 3; i++) {
                int task = tid + i * 256;
                if (task < F_BTASKS) pb[i] = loadB(task, k0 + 32);
            }
        }

        // 2 k16 steps over the 32-k tile (reads buffer p)
        #pragma unroll
        for (int ks = 0; ks < 2; ks++) {
            int kb2 = ks * 8;
            unsigned afr[4][4], bfr[5][2];
            #pragma unroll
            for (int ma = 0; ma < 4; ma++) {
                int r0 = warpM * 64 + ma * 16;
                afr[ma][0] = As[p][(r0 + g)     * F_APADU + kb2 + t];
                afr[ma][1] = As[p][(r0 + g + 8) * F_APADU + kb2 + t];
                afr[ma][2] = As[p][(r0 + g)     * F_APADU + kb2 + 4 + t];
                afr[ma][3] = As[p][(r0 + g + 8) * F_APADU + kb2 + 4 + t];
            }
            #pragma unroll
            for (int na = 0; na < 5; na++) {
                int c0 = warpN * 40 + na * 8;
                bfr[na][0] = Bs[p][(kb2 + t)     * F_BPADU + c0 + g];
                bfr[na][1] = Bs[p][(kb2 + 4 + t) * F_BPADU + c0 + g];
            }
            #pragma unroll
            for (int ma = 0; ma < 4; ma++)
                #pragma unroll
                for (int na = 0; na < 5; na++)
                    mma_bf16(acc[ma][na], afr[ma], bfr[na]);
        }
        p ^= 1;
    }

    // epilogue: cols <128 -> bias+relu -> g_h ; cols >=128 -> raw -> g_UV
    #pragma unroll
    for (int ma = 0; ma < 4; ma++) {
        int rbase = by * 128 + warpM * 64 + ma * 16;
        #pragma unroll
        for (int na = 0; na < 5; na++) {
            int colBlk = warpN * 40 + na * 8 + t * 2;     // 0..158
            if (colBlk < 128) {
                int col = bx * 128 + colBlk;
                float b0 = __ldg(bias + col), b1 = __ldg(bias + col + 1);
                float2 v;
                v.x = fmaxf(acc[ma][na][0] + b0, 0.f);
                v.y = fmaxf(acc[ma][na][1] + b1, 0.f);
                *(float2*)&g_h[(size_t)(rbase + g) * GG + col] = v;
                v.x = fmaxf(acc[ma][na][2] + b0, 0.f);
                v.y = fmaxf(acc[ma][na][3] + b1, 0.f);
                *(float2*)&g_h[(size_t)(rbase + g + 8) * GG + col] = v;
            } else {
                int col = bx * 32 + (colBlk - 128);       // U at 0..31, V at 32..63
                float2 v;
                v.x = acc[ma][na][0]; v.y = acc[ma][na][1];
                *(float2*)&g_UV[(size_t)(rbase + g) * 64 + col] = v;
                v.x = acc[ma][na][2]; v.y = acc[ma][na][3];
                *(float2*)&g_UV[(size_t)(rbase + g + 8) * 64 + col] = v;
            }
        }
    }
}

// ======================================================================
// K2b (bf16 mma): gate = sigmoid(h @ W2 + b2); gateU = gate * U
// Block = 64 tokens, 256 threads (8 warps, 2x4), N=32, K=256 (16 k16 steps).
// ======================================================================
#define H2_PADU 132    // u32 per hs row (128 used + 4 pad): bank = 4g+t, distinct
__global__ void __launch_bounds__(256) k2b_mma(
    const float* __restrict__ W2,      // (256 x 32)
    const float* __restrict__ b2)      // (32)
{
    __shared__ unsigned hs[64 * H2_PADU];   // 33.8 KB

    const int tid  = threadIdx.x;
    const int by   = blockIdx.x;            // token tile 0..255
    const int wid  = tid >> 5;
    const int lane = tid & 31;
    const int g    = lane >> 2;             // 0..7
    const int t    = lane & 3;              // 0..3
    const int warpM = wid >> 2;             // 0..1 -> 32 rows
    const int warpN = wid & 3;              // 0..3 -> 8 cols

    const int token0 = by * 64;

    // load h tile (64 x 256 f32) -> packed bf16 smem
    #pragma unroll
    for (int i = 0; i < 16; i++) {
        int flat = tid + i * 256;           // 0..4095
        int row  = flat >> 6;               // 0..63
        int c4   = (flat & 63) * 4;         // 0..252
        float4 v = *(const float4*)(g_h + (size_t)(token0 + row) * GG + c4);
        uint2 pv;
        pv.x = pack_bf16x2(v.x, v.y);
        pv.y = pack_bf16x2(v.z, v.w);
        *(uint2*)&hs[row * H2_PADU + (c4 >> 1)] = pv;
    }
    __syncthreads();

    // gate GEMM: M=64, N=32, K=256
    float acc2[2][4];
    #pragma unroll
    for (int ma = 0; ma < 2; ma++)
        #pragma unroll
        for (int i = 0; i < 4; i++) acc2[ma][i] = 0.f;

    const int n = warpN * 8 + g;
    #pragma unroll
    for (int kstep = 0; kstep < 16; kstep++) {
        int kb2u = kstep * 8;
        unsigned afr[2][4], bfr[2];
        #pragma unroll
        for (int ma = 0; ma < 2; ma++) {
            int r0 = warpM * 32 + ma * 16;
            afr[ma][0] = hs[(r0 + g)     * H2_PADU + kb2u + t];
            afr[ma][1] = hs[(r0 + g + 8) * H2_PADU + kb2u + t];
            afr[ma][2] = hs[(r0 + g)     * H2_PADU + kb2u + 4 + t];
            afr[ma][3] = hs[(r0 + g + 8) * H2_PADU + kb2u + 4 + t];
        }
        int k0f = kstep * 16 + 2 * t;
        bfr[0] = pack_bf16x2(__ldg(W2 + (size_t)k0f * 32 + n),
                             __ldg(W2 + (size_t)(k0f + 1) * 32 + n));
        bfr[1] = pack_bf16x2(__ldg(W2 + (size_t)(k0f + 8) * 32 + n),
                             __ldg(W2 + (size_t)(k0f + 9) * 32 + n));
        #pragma unroll
        for (int ma = 0; ma < 2; ma++)
            mma_bf16(acc2[ma], afr[ma], bfr);
    }

    // epilogue: sigmoid(+b2) * U  -> g_gateU
    #pragma unroll
    for (int ma = 0; ma < 2; ma++) {
        #pragma unroll
        for (int j = 0; j < 4; j++) {
            int rowL = warpM * 32 + ma * 16 + g + (j >> 1) * 8;
            int col  = warpN * 8 + t * 2 + (j & 1);
            float v = acc2[ma][j] + __ldg(b2 + col);
            float gate = 1.f / (1.f + expf(-v));
            float u = __ldg(g_UV + (size_t)(token0 + rowL) * 64 + col);
            g_gateU[(size_t)(token0 + rowL) * RR + col] = gate * u;
        }
    }
}

// ======================================================================
// K3a: segmented inclusive cumsum of V over L (NSEG=32 segments per batch).
// ======================================================================
__global__ void __launch_bounds__(1024) k3a_scan()
{
    const int b   = blockIdx.x >> 5;      // NSEG = 32
    const int seg = blockIdx.x & 31;
    __shared__ float buf[32][33];

    const int tid  = threadIdx.x;
    const int lane = tid & 31;
    const int warp = tid >> 5;
    const int l    = tid >> 5;
    const int r    = tid & 31;

    const float* Vb = g_UV + (size_t)(b * LL + seg * SEG) * 64 + 32;
    float*       Sb = g_glob + (size_t)(b * LL + seg * SEG) * RR;

    float carry = 0.f;
    for (int c = 0; c < SEG / 32; c++) {
        buf[l][r] = Vb[(size_t)(c * 32 + l) * 64 + r];
        __syncthreads();
        float v = buf[lane][warp];
        #pragma unroll
        for (int off = 1; off < 32; off <<= 1) {
            float n = __shfl_up_sync(0xffffffffu, v, off);
            if (lane >= off) v += n;
        }
        v += carry;
        carry = __shfl_sync(0xffffffffu, v, 31);
        buf[lane][warp] = v;
        __syncthreads();
        Sb[c * 1024 + tid] = buf[l][r];
        __syncthreads();
    }
    if (lane == 0)
        g_segsum[(b * NSEG + seg) * RR + warp] = carry;
}

// ======================================================================
// K4: out = (gateU*(S+off)) @ out_w + out_b + depthwise_conv3(x)
// TF32 mma: block = 64 tokens x 128 dcols, K=32 (single tile). (R10 form)
// ======================================================================
#define T4_APAD 36
#define T4_BPAD 136
__global__ void __launch_bounds__(256, 3) k4_mma(
    const float* __restrict__ x,
    const float* __restrict__ conv_w,   // (1024 x 3)
    const float* __restrict__ out_w,    // (32 x 1024)
    const float* __restrict__ out_b,    // (1024)
    float* __restrict__ out)
{
    __shared__ unsigned Gs[64 * T4_APAD];
    __shared__ unsigned Ws[32 * T4_BPAD];

    const int tid  = threadIdx.x;
    const int bx   = blockIdx.x;            // d tile 0..7
    const int by   = blockIdx.y;            // token tile 0..255
    const int wid  = tid >> 5;
    const int lane = tid & 31;
    const int g    = lane >> 2;
    const int tig  = lane & 3;
    const int warpM = wid >> 2;             // 0..1 -> 32 rows
    const int warpN = wid & 3;              // 0..3 -> 32 cols

    const int token0 = by * 64;
    const int d0     = bx * 128;

    const int b   = token0 >> 12;
    const int seg = (token0 & (LL - 1)) >> 7;     // SEG = 128
    const int r   = tid & 31;
    float soff = 0.f;
    for (int s = 0; s < seg; s++)
        soff += g_segsum[(b * NSEG + s) * RR + r];

    #pragma unroll
    for (int i = 0; i < 8; i++) {
        int flat  = tid + i * 256;
        int row   = flat >> 5;
        size_t gi = (size_t)(token0 + row) * RR + r;
        float S = g_glob[gi] + soff;
        Gs[row * T4_APAD + r] = f2tf32(g_gateU[gi] * S);
    }
    #pragma unroll
    for (int i = 0; i < 16; i++) {
        int flat = tid + i * 256;
        int rr   = flat >> 7;
        int c    = flat & 127;
        Ws[rr * T4_BPAD + c] = f2tf32(__ldg(out_w + (size_t)rr * DD + d0 + c));
    }
    __syncthreads();

    float acc[2][4][4];
    #pragma unroll
    for (int ma = 0; ma < 2; ma++)
        #pragma unroll
        for (int na = 0; na < 4; na++)
            #pragma unroll
            for (int i = 0; i < 4; i++) acc[ma][na][i] = 0.f;

    #pragma unroll
    for (int ks = 0; ks < 4; ks++) {
        int kb = ks * 8;
        unsigned afr[2][4], bfr[4][2];
        #pragma unroll
        for (int ma = 0; ma < 2; ma++) {
            int r0 = warpM * 32 + ma * 16;
            afr[ma][0] = Gs[(r0 + g)     * T4_APAD + kb + tig];
            afr[ma][1] = Gs[(r0 + g + 8) * T4_APAD + kb + tig];
            afr[ma][2] = Gs[(r0 + g)     * T4_APAD + kb + tig + 4];
            afr[ma][3] = Gs[(r0 + g + 8) * T4_APAD + kb + tig + 4];
        }
        #pragma unroll
        for (int na = 0; na < 4; na++) {
            int c0 = warpN * 32 + na * 8;
            bfr[na][0] = Ws[(kb + tig)     * T4_BPAD + c0 + g];
            bfr[na][1] = Ws[(kb + tig + 4) * T4_BPAD + c0 + g];
        }
        #pragma unroll
        for (int ma = 0; ma < 2; ma++)
            #pragma unroll
            for (int na = 0; na < 4; na++)
                mma_tf32(acc[ma][na], afr[ma], bfr[na]);
    }

    #pragma unroll
    for (int na = 0; na < 4; na++) {
        int c = d0 + warpN * 32 + na * 8 + tig * 2;
        float2 w01 = *(const float2*)(conv_w + c * 3);
        float2 w23 = *(const float2*)(conv_w + c * 3 + 2);
        float2 w45 = *(const float2*)(conv_w + c * 3 + 4);
        float2 bb  = *(const float2*)(out_b + c);

        #pragma unroll
        for (int ma = 0; ma < 2; ma++) {
            #pragma unroll
            for (int rh = 0; rh < 2; rh++) {
                int token = token0 + warpM * 32 + ma * 16 + g + rh * 8;
                int lpos  = token & (LL - 1);
                const float* xr = x + (size_t)token * DD + c;
                float2 xc = *(const float2*)xr;
                float2 xm = (lpos > 0)      ? *(const float2*)(xr - DD) : make_float2(0.f, 0.f);
                float2 xp = (lpos < LL - 1) ? *(const float2*)(xr + DD) : make_float2(0.f, 0.f);
                float2 o;
                o.x = acc[ma][na][rh * 2 + 0] + bb.x
                    + w01.x * xm.x + w01.y * xc.x + w23.x * xp.x;
                o.y = acc[ma][na][rh * 2 + 1] + bb.y
                    + w23.y * xm.y + w45.x * xc.y + w45.y * xp.y;
                *(float2*)(out + (size_t)token * DD + c) = o;
            }
        }
    }
}

// ======================================================================
extern "C" void kernel_launch(void* const* d_in, const int* in_sizes, int n_in,
                              void* d_out, int out_size)
{
    const float* x       = (const float*)d_in[0];
    const float* gate_w1 = (const float*)d_in[1];
    const float* gate_b1 = (const float*)d_in[2];
    const float* gate_w2 = (const float*)d_in[3];
    const float* gate_b2 = (const float*)d_in[4];
    const float* U_w     = (const float*)d_in[5];
    const float* V_w     = (const float*)d_in[6];
    const float* conv_w  = (const float*)d_in[7];
    const float* out_w   = (const float*)d_in[8];
    const float* out_b   = (const float*)d_in[9];
    float* out = (float*)d_out;

    // K12: h = relu(x@W1+b1) AND UV = x@[Uw|Vw]  (bf16 mma, BM=128)
    k12_bf16<<<dim3(2, MTOK / 128), 256>>>(x, gate_w1, gate_b1, U_w, V_w);
    // K2b: gateU (bf16 mma)
    k2b_mma<<<MTOK / 64, 256>>>(gate_w2, gate_b2);
    // K3a: segmented cumsum of V (totals to g_segsum)
    k3a_scan<<<BB * NSEG, 1024>>>();
    // K4: out = glob@out_w + bias + conv  (tf32 mma; k3c+k3b fused; 64-token tiles)
    k4_mma<<<dim3(DD / 128, MTOK / 64), 256>>>(x, conv_w, out_w, out_b, out);
}

// round 17
// speedup vs baseline: 1.2487x; 1.2363x over previous
#include <cuda_runtime.h>
#include <cuda_bf16.h>
#include <math.h>

// Problem constants
#define BB 4
#define LL 4096
#define DD 1024
#define RR 32
#define GG 256
#define MTOK (BB*LL)          // 16384 tokens
#define NSEG 32
#define SEG  (LL/NSEG)        // 128

// ---------------- scratch (static device memory; no allocations) ----------------
__device__ float g_h[MTOK * GG];        // 16 MB : relu(x@W1+b1)
__device__ float g_UV[MTOK * 64];       //  4 MB : cols 0..31 = U, 32..63 = V
__device__ float g_gateU[MTOK * RR];    //  2 MB : sigmoid(h@W2+b2) * U
__device__ float g_glob[MTOK * RR];     //  2 MB : local (per-segment) cumsum of V
__device__ float g_segsum[BB * NSEG * RR];

// ---------------- helpers ----------------
__device__ __forceinline__ unsigned f2tf32(float f) {
    unsigned r;
    asm("cvt.rna.tf32.f32 %0, %1;" : "=r"(r) : "f"(f));
    return r;
}

__device__ __forceinline__ unsigned pack_bf16x2(float lo, float hi) {
    __nv_bfloat162 h2 = __floats2bfloat162_rn(lo, hi);   // lo -> low half
    return *(unsigned*)&h2;
}

__device__ __forceinline__ void mma_tf32(float* d, const unsigned* a, const unsigned* b) {
    asm volatile(
        "mma.sync.aligned.m16n8k8.row.col.f32.tf32.tf32.f32 "
        "{%0,%1,%2,%3}, {%4,%5,%6,%7}, {%8,%9}, {%0,%1,%2,%3};"
        : "+f"(d[0]), "+f"(d[1]), "+f"(d[2]), "+f"(d[3])
        : "r"(a[0]), "r"(a[1]), "r"(a[2]), "r"(a[3]), "r"(b[0]), "r"(b[1]));
}

__device__ __forceinline__ void mma_bf16(float* d, const unsigned* a, const unsigned* b) {
    asm volatile(
        "mma.sync.aligned.m16n8k16.row.col.f32.bf16.bf16.f32 "
        "{%0,%1,%2,%3}, {%4,%5,%6,%7}, {%8,%9}, {%0,%1,%2,%3};"
        : "+f"(d[0]), "+f"(d[1]), "+f"(d[2]), "+f"(d[3])
        : "r"(a[0]), "r"(a[1]), "r"(a[2]), "r"(a[3]), "r"(b[0]), "r"(b[1]));
}

// ======================================================================
// K12 (fused K1+K2a), BF16 mma m16n8k16, double-buffered (R14 form, proven):
//   bx=0:  h[:,0:128]   and U = x@Uw
//   bx=1:  h[:,128:256] and V = x@Vw
// Block 64(M) x 160(N) x 32(K).  8 warps (2x4), warp tile 32x40 (2x5 atoms).
// ======================================================================
#define F_APADU 20     // u32 per As row (16 used + 4 pad) -> conflict-free frags
#define F_BPADU 168    // u32 per Bs k2-row (160 used + 8 pad)
#define F_BTASKS 640   // 16 k2-rows * 40 col4 groups
__global__ void __launch_bounds__(256, 2) k12_bf16(
    const float* __restrict__ A,      // x       (M x 1024)
    const float* __restrict__ W,      // gate_w1 (1024 x 256)
    const float* __restrict__ bias,   // gate_b1 (256)
    const float* __restrict__ Uw,     // (1024 x 32)
    const float* __restrict__ Vw)     // (1024 x 32)
{
    const int K = DD;
    __shared__ unsigned As[2][64 * F_APADU];   // 2 x 5.1 KB
    __shared__ unsigned Bs[2][16 * F_BPADU];   // 2 x 10.8 KB

    const int tid  = threadIdx.x;
    const int bx   = blockIdx.x;           // 0..1 (h half + U/V select)
    const int by   = blockIdx.y;           // M tile 0..255
    const int wid  = tid >> 5;
    const int lane = tid & 31;
    const int g    = lane >> 2;            // 0..7
    const int t    = lane & 3;             // 0..3
    const int warpM = wid >> 2;            // 0..1 -> 32 rows
    const int warpN = wid & 3;             // 0..3 -> 40 cols

    const float* Aptr  = A + (size_t)by * 64 * K;
    const float* Wptr  = W + bx * 128;
    const float* UVptr = bx ? Vw : Uw;

    const int aRow = tid >> 3;             // 0..31 (x2 -> 64 rows)
    const int aC4  = (tid & 7) * 4;
    const int aK2  = (tid & 7) * 2;

    float acc[2][5][4];
    #pragma unroll
    for (int ma = 0; ma < 2; ma++)
        #pragma unroll
        for (int na = 0; na < 5; na++)
            #pragma unroll
            for (int i = 0; i < 4; i++) acc[ma][na][i] = 0.f;

    float4 pa[2];
    float4 pbe[3], pbo[3];
    #pragma unroll
    for (int i = 0; i < 2; i++)
        pa[i] = *(const float4*)(Aptr + (size_t)(aRow + i * 32) * K + aC4);
    #pragma unroll
    for (int i = 0; i < 3; i++) {
        int task = tid + i * 256;
        if (task < F_BTASKS) {
            int k2 = task / 40;
            int c4 = (task % 40) * 4;
            const float* base = (c4 < 128)
                ? (Wptr + (size_t)(2 * k2) * GG + c4)
                : (UVptr + (size_t)(2 * k2) * 32 + (c4 - 128));
            int stride = (c4 < 128) ? GG : 32;
            pbe[i] = *(const float4*)base;
            pbo[i] = *(const float4*)(base + stride);
        }
    }

    int p = 0;
    for (int k0 = 0; k0 < K; k0 += 32) {
        #pragma unroll
        for (int i = 0; i < 2; i++) {
            int row = aRow + i * 32;
            uint2 v;
            v.x = pack_bf16x2(pa[i].x, pa[i].y);
            v.y = pack_bf16x2(pa[i].z, pa[i].w);
            *(uint2*)&As[p][row * F_APADU + aK2] = v;
        }
        #pragma unroll
        for (int i = 0; i < 3; i++) {
            int task = tid + i * 256;
            if (task < F_BTASKS) {
                int k2 = task / 40;
                int c4 = (task % 40) * 4;
                uint4 v;
                v.x = pack_bf16x2(pbe[i].x, pbo[i].x);
                v.y = pack_bf16x2(pbe[i].y, pbo[i].y);
                v.z = pack_bf16x2(pbe[i].z, pbo[i].z);
                v.w = pack_bf16x2(pbe[i].w, pbo[i].w);
                *(uint4*)&Bs[p][k2 * F_BPADU + c4] = v;
            }
        }
        __syncthreads();

        if (k0 + 32 < K) {
            #pragma unroll
            for (int i = 0; i < 2; i++)
                pa[i] = *(const float4*)(Aptr + (size_t)(aRow + i * 32) * K + (k0 + 32) + aC4);
            #pragma unroll
            for (int i = 0; i < 3; i++) {
                int task = tid + i * 256;
                if (task < F_BTASKS) {
                    int k2 = task / 40;
                    int c4 = (task % 40) * 4;
                    int krow = k0 + 32 + 2 * k2;
                    const float* base = (c4 < 128)
                        ? (Wptr + (size_t)krow * GG + c4)
                        : (UVptr + (size_t)krow * 32 + (c4 - 128));
                    int stride = (c4 < 128) ? GG : 32;
                    pbe[i] = *(const float4*)base;
                    pbo[i] = *(const float4*)(base + stride);
                }
            }
        }

        #pragma unroll
        for (int ks = 0; ks < 2; ks++) {
            int kb2 = ks * 8;
            unsigned afr[2][4], bfr[5][2];
            #pragma unroll
            for (int ma = 0; ma < 2; ma++) {
                int r0 = warpM * 32 + ma * 16;
                afr[ma][0] = As[p][(r0 + g)     * F_APADU + kb2 + t];
                afr[ma][1] = As[p][(r0 + g + 8) * F_APADU + kb2 + t];
                afr[ma][2] = As[p][(r0 + g)     * F_APADU + kb2 + 4 + t];
                afr[ma][3] = As[p][(r0 + g + 8) * F_APADU + kb2 + 4 + t];
            }
            #pragma unroll
            for (int na = 0; na < 5; na++) {
                int c0 = warpN * 40 + na * 8;
                bfr[na][0] = Bs[p][(kb2 + t)     * F_BPADU + c0 + g];
                bfr[na][1] = Bs[p][(kb2 + 4 + t) * F_BPADU + c0 + g];
            }
            #pragma unroll
            for (int ma = 0; ma < 2; ma++)
                #pragma unroll
                for (int na = 0; na < 5; na++)
                    mma_bf16(acc[ma][na], afr[ma], bfr[na]);
        }
        p ^= 1;
    }

    // epilogue: cols <128 -> bias+relu -> g_h ; cols >=128 -> raw -> g_UV
    #pragma unroll
    for (int ma = 0; ma < 2; ma++) {
        int rbase = by * 64 + warpM * 32 + ma * 16;
        #pragma unroll
        for (int na = 0; na < 5; na++) {
            int colBlk = warpN * 40 + na * 8 + t * 2;     // 0..158
            if (colBlk < 128) {
                int col = bx * 128 + colBlk;
                float b0 = __ldg(bias + col), b1 = __ldg(bias + col + 1);
                float2 v;
                v.x = fmaxf(acc[ma][na][0] + b0, 0.f);
                v.y = fmaxf(acc[ma][na][1] + b1, 0.f);
                *(float2*)&g_h[(size_t)(rbase + g) * GG + col] = v;
                v.x = fmaxf(acc[ma][na][2] + b0, 0.f);
                v.y = fmaxf(acc[ma][na][3] + b1, 0.f);
                *(float2*)&g_h[(size_t)(rbase + g + 8) * GG + col] = v;
            } else {
                int col = bx * 32 + (colBlk - 128);       // U at 0..31, V at 32..63
                float2 v;
                v.x = acc[ma][na][0]; v.y = acc[ma][na][1];
                *(float2*)&g_UV[(size_t)(rbase + g) * 64 + col] = v;
                v.x = acc[ma][na][2]; v.y = acc[ma][na][3];
                *(float2*)&g_UV[(size_t)(rbase + g + 8) * 64 + col] = v;
            }
        }
    }
}

// ======================================================================
// K2b (bf16 mma): gate = sigmoid(h @ W2 + b2); gateU = gate * U
// Block = 64 tokens, 256 threads (8 warps, 2x4), N=32, K=256 (16 k16 steps).
// ======================================================================
#define H2_PADU 132    // u32 per hs row (128 used + 4 pad): bank = 4g+t, distinct
__global__ void __launch_bounds__(256) k2b_mma(
    const float* __restrict__ W2,      // (256 x 32)
    const float* __restrict__ b2)      // (32)
{
    __shared__ unsigned hs[64 * H2_PADU];   // 33.8 KB

    const int tid  = threadIdx.x;
    const int by   = blockIdx.x;            // token tile 0..255
    const int wid  = tid >> 5;
    const int lane = tid & 31;
    const int g    = lane >> 2;             // 0..7
    const int t    = lane & 3;              // 0..3
    const int warpM = wid >> 2;             // 0..1 -> 32 rows
    const int warpN = wid & 3;              // 0..3 -> 8 cols

    const int token0 = by * 64;

    // load h tile (64 x 256 f32) -> packed bf16 smem
    #pragma unroll
    for (int i = 0; i < 16; i++) {
        int flat = tid + i * 256;           // 0..4095
        int row  = flat >> 6;               // 0..63
        int c4   = (flat & 63) * 4;         // 0..252
        float4 v = *(const float4*)(g_h + (size_t)(token0 + row) * GG + c4);
        uint2 pv;
        pv.x = pack_bf16x2(v.x, v.y);
        pv.y = pack_bf16x2(v.z, v.w);
        *(uint2*)&hs[row * H2_PADU + (c4 >> 1)] = pv;
    }
    __syncthreads();

    // gate GEMM: M=64, N=32, K=256
    float acc2[2][4];
    #pragma unroll
    for (int ma = 0; ma < 2; ma++)
        #pragma unroll
        for (int i = 0; i < 4; i++) acc2[ma][i] = 0.f;

    const int n = warpN * 8 + g;
    #pragma unroll
    for (int kstep = 0; kstep < 16; kstep++) {
        int kb2u = kstep * 8;
        unsigned afr[2][4], bfr[2];
        #pragma unroll
        for (int ma = 0; ma < 2; ma++) {
            int r0 = warpM * 32 + ma * 16;
            afr[ma][0] = hs[(r0 + g)     * H2_PADU + kb2u + t];
            afr[ma][1] = hs[(r0 + g + 8) * H2_PADU + kb2u + t];
            afr[ma][2] = hs[(r0 + g)     * H2_PADU + kb2u + 4 + t];
            afr[ma][3] = hs[(r0 + g + 8) * H2_PADU + kb2u + 4 + t];
        }
        int k0f = kstep * 16 + 2 * t;
        bfr[0] = pack_bf16x2(__ldg(W2 + (size_t)k0f * 32 + n),
                             __ldg(W2 + (size_t)(k0f + 1) * 32 + n));
        bfr[1] = pack_bf16x2(__ldg(W2 + (size_t)(k0f + 8) * 32 + n),
                             __ldg(W2 + (size_t)(k0f + 9) * 32 + n));
        #pragma unroll
        for (int ma = 0; ma < 2; ma++)
            mma_bf16(acc2[ma], afr[ma], bfr);
    }

    // epilogue: sigmoid(+b2) * U  -> g_gateU
    #pragma unroll
    for (int ma = 0; ma < 2; ma++) {
        #pragma unroll
        for (int j = 0; j < 4; j++) {
            int rowL = warpM * 32 + ma * 16 + g + (j >> 1) * 8;
            int col  = warpN * 8 + t * 2 + (j & 1);
            float v = acc2[ma][j] + __ldg(b2 + col);
            float gate = 1.f / (1.f + expf(-v));
            float u = __ldg(g_UV + (size_t)(token0 + rowL) * 64 + col);
            g_gateU[(size_t)(token0 + rowL) * RR + col] = gate * u;
        }
    }
}

// ======================================================================
// K3a: segmented inclusive cumsum of V over L (NSEG=32 segments per batch).
// ======================================================================
__global__ void __launch_bounds__(1024) k3a_scan()
{
    const int b   = blockIdx.x >> 5;      // NSEG = 32
    const int seg = blockIdx.x & 31;
    __shared__ float buf[32][33];

    const int tid  = threadIdx.x;
    const int lane = tid & 31;
    const int warp = tid >> 5;
    const int l    = tid >> 5;
    const int r    = tid & 31;

    const float* Vb = g_UV + (size_t)(b * LL + seg * SEG) * 64 + 32;
    float*       Sb = g_glob + (size_t)(b * LL + seg * SEG) * RR;

    float carry = 0.f;
    for (int c = 0; c < SEG / 32; c++) {
        buf[l][r] = Vb[(size_t)(c * 32 + l) * 64 + r];
        __syncthreads();
        float v = buf[lane][warp];
        #pragma unroll
        for (int off = 1; off < 32; off <<= 1) {
            float n = __shfl_up_sync(0xffffffffu, v, off);
            if (lane >= off) v += n;
        }
        v += carry;
        carry = __shfl_sync(0xffffffffu, v, 31);
        buf[lane][warp] = v;
        __syncthreads();
        Sb[c * 1024 + tid] = buf[l][r];
        __syncthreads();
    }
    if (lane == 0)
        g_segsum[(b * NSEG + seg) * RR + warp] = carry;
}

// ======================================================================
// K4: out = (gateU*(S+off)) @ out_w + out_b + depthwise_conv3(x)
// TF32 mma: block = 64 tokens x 128 dcols, K=32 (single tile).
// Epilogue: x conv taps fetched via warp shuffle (xm/xp from neighbor
// lanes' xc registers); real loads only at the two 16-row block seams.
// ======================================================================
#define T4_APAD 36
#define T4_BPAD 136
__global__ void __launch_bounds__(256, 3) k4_mma(
    const float* __restrict__ x,
    const float* __restrict__ conv_w,   // (1024 x 3)
    const float* __restrict__ out_w,    // (32 x 1024)
    const float* __restrict__ out_b,    // (1024)
    float* __restrict__ out)
{
    __shared__ unsigned Gs[64 * T4_APAD];
    __shared__ unsigned Ws[32 * T4_BPAD];

    const int tid  = threadIdx.x;
    const int bx   = blockIdx.x;            // d tile 0..7
    const int by   = blockIdx.y;            // token tile 0..255
    const int wid  = tid >> 5;
    const int lane = tid & 31;
    const int g    = lane >> 2;
    const int tig  = lane & 3;
    const int warpM = wid >> 2;             // 0..1 -> 32 rows
    const int warpN = wid & 3;              // 0..3 -> 32 cols

    const int token0 = by * 64;
    const int d0     = bx * 128;

    const int b   = token0 >> 12;
    const int seg = (token0 & (LL - 1)) >> 7;     // SEG = 128
    const int r   = tid & 31;
    float soff = 0.f;
    for (int s = 0; s < seg; s++)
        soff += g_segsum[(b * NSEG + s) * RR + r];

    #pragma unroll
    for (int i = 0; i < 8; i++) {
        int flat  = tid + i * 256;
        int row   = flat >> 5;
        size_t gi = (size_t)(token0 + row) * RR + r;
        float S = g_glob[gi] + soff;
        Gs[row * T4_APAD + r] = f2tf32(g_gateU[gi] * S);
    }
    #pragma unroll
    for (int i = 0; i < 16; i++) {
        int flat = tid + i * 256;
        int rr   = flat >> 7;
        int c    = flat & 127;
        Ws[rr * T4_BPAD + c] = f2tf32(__ldg(out_w + (size_t)rr * DD + d0 + c));
    }
    __syncthreads();

    float acc[2][4][4];
    #pragma unroll
    for (int ma = 0; ma < 2; ma++)
        #pragma unroll
        for (int na = 0; na < 4; na++)
            #pragma unroll
            for (int i = 0; i < 4; i++) acc[ma][na][i] = 0.f;

    #pragma unroll
    for (int ks = 0; ks < 4; ks++) {
        int kb = ks * 8;
        unsigned afr[2][4], bfr[4][2];
        #pragma unroll
        for (int ma = 0; ma < 2; ma++) {
            int r0 = warpM * 32 + ma * 16;
            afr[ma][0] = Gs[(r0 + g)     * T4_APAD + kb + tig];
            afr[ma][1] = Gs[(r0 + g + 8) * T4_APAD + kb + tig];
            afr[ma][2] = Gs[(r0 + g)     * T4_APAD + kb + tig + 4];
            afr[ma][3] = Gs[(r0 + g + 8) * T4_APAD + kb + tig + 4];
        }
        #pragma unroll
        for (int na = 0; na < 4; na++) {
            int c0 = warpN * 32 + na * 8;
            bfr[na][0] = Ws[(kb + tig)     * T4_BPAD + c0 + g];
            bfr[na][1] = Ws[(kb + tig + 4) * T4_BPAD + c0 + g];
        }
        #pragma unroll
        for (int ma = 0; ma < 2; ma++)
            #pragma unroll
            for (int na = 0; na < 4; na++)
                mma_tf32(acc[ma][na], afr[ma], bfr[na]);
    }

    // ---- epilogue: conv taps via warp shuffle ----
    const unsigned FULL = 0xffffffffu;
    #pragma unroll
    for (int na = 0; na < 4; na++) {
        int c = d0 + warpN * 32 + na * 8 + tig * 2;
        float2 w01 = *(const float2*)(conv_w + c * 3);      // (m0, c0)
        float2 w23 = *(const float2*)(conv_w + c * 3 + 2);  // (p0, m1)
        float2 w45 = *(const float2*)(conv_w + c * 3 + 4);  // (c1, p1)
        float2 bb  = *(const float2*)(out_b + c);

        #pragma unroll
        for (int ma = 0; ma < 2; ma++) {
            int r0 = token0 + warpM * 32 + ma * 16 + g;     // rh0 row; rh1 = r0+8
            const float* xr0 = x + (size_t)r0 * DD + c;
            float2 xc0 = *(const float2*)xr0;
            float2 xc1 = *(const float2*)(xr0 + 8 * DD);

            float2 xm0, xm1, xp0, xp1;
            // xm0: row r0-1.  g>=1: neighbor's xc0 ; g==0: real (masked) load
            xm0.x = __shfl_up_sync(FULL, xc0.x, 4);
            xm0.y = __shfl_up_sync(FULL, xc0.y, 4);
            // xm1: row r0+7.  g>=1: neighbor's xc1 ; g==0: lane 28+t's xc0
            {
                float ax = __shfl_up_sync(FULL, xc1.x, 4);
                float ay = __shfl_up_sync(FULL, xc1.y, 4);
                float bx2 = __shfl_sync(FULL, xc0.x, 28 + tig);
                float by2 = __shfl_sync(FULL, xc0.y, 28 + tig);
                xm1.x = (g == 0) ? bx2 : ax;
                xm1.y = (g == 0) ? by2 : ay;
            }
            // xp0: row r0+1.  g<=6: neighbor's xc0 ; g==7: lane t's xc1
            {
                float ax = __shfl_down_sync(FULL, xc0.x, 4);
                float ay = __shfl_down_sync(FULL, xc0.y, 4);
                float bx2 = __shfl_sync(FULL, xc1.x, tig);
                float by2 = __shfl_sync(FULL, xc1.y, tig);
                xp0.x = (g == 7) ? bx2 : ax;
                xp0.y = (g == 7) ? by2 : ay;
            }
            // xp1: row r0+9.  g<=6: neighbor's xc1 ; g==7: real (masked) load
            xp1.x = __shfl_down_sync(FULL, xc1.x, 4);
            xp1.y = __shfl_down_sync(FULL, xc1.y, 4);

            if (g == 0) {
                int lpos0 = r0 & (LL - 1);
                xm0 = (lpos0 > 0) ? *(const float2*)(xr0 - DD)
                                  : make_float2(0.f, 0.f);
            }
            if (g == 7) {
                int lpos1 = (r0 + 8) & (LL - 1);
                xp1 = (lpos1 < LL - 1) ? *(const float2*)(xr0 + 9 * DD)
                                       : make_float2(0.f, 0.f);
            }

            float2 o0, o1;
            o0.x = acc[ma][na][0] + bb.x + w01.x * xm0.x + w01.y * xc0.x + w23.x * xp0.x;
            o0.y = acc[ma][na][1] + bb.y + w23.y * xm0.y + w45.x * xc0.y + w45.y * xp0.y;
            o1.x = acc[ma][na][2] + bb.x + w01.x * xm1.x + w01.y * xc1.x + w23.x * xp1.x;
            o1.y = acc[ma][na][3] + bb.y + w23.y * xm1.y + w45.x * xc1.y + w45.y * xp1.y;
            *(float2*)(out + (size_t)r0 * DD + c) = o0;
            *(float2*)(out + (size_t)(r0 + 8) * DD + c) = o1;
        }
    }
}

// ======================================================================
extern "C" void kernel_launch(void* const* d_in, const int* in_sizes, int n_in,
                              void* d_out, int out_size)
{
    const float* x       = (const float*)d_in[0];
    const float* gate_w1 = (const float*)d_in[1];
    const float* gate_b1 = (const float*)d_in[2];
    const float* gate_w2 = (const float*)d_in[3];
    const float* gate_b2 = (const float*)d_in[4];
    const float* U_w     = (const float*)d_in[5];
    const float* V_w     = (const float*)d_in[6];
    const float* conv_w  = (const float*)d_in[7];
    const float* out_w   = (const float*)d_in[8];
    const float* out_b   = (const float*)d_in[9];
    float* out = (float*)d_out;

    // K12: h = relu(x@W1+b1) AND UV = x@[Uw|Vw]  (bf16 mma, R14 form)
    k12_bf16<<<dim3(2, MTOK / 64), 256>>>(x, gate_w1, gate_b1, U_w, V_w);
    // K2b: gateU (bf16 mma)
    k2b_mma<<<MTOK / 64, 256>>>(gate_w2, gate_b2);
    // K3a: segmented cumsum of V (totals to g_segsum)
    k3a_scan<<<BB * NSEG, 1024>>>();
    // K4: out = glob@out_w + bias + conv  (tf32 mma; shuffle conv taps)
    k4_mma<<<dim3(DD / 128, MTOK / 64), 256>>>(x, conv_w, out_w, out_b, out);
}